// round 15
// baseline (speedup 1.0000x reference)
#include <cuda_runtime.h>
#include <cuda_fp16.h>
#include <cstdint>

// LocallyConnected2D B=64,H=W=32,C=64,3x3,s1 -> P=900, K=576, O=64
// Kernel 1: x fp32->fp16 once into __device__ scratch; signals dependents (PDL).
// Kernel 2 (= R13 config, measured 33.1us): grid 450, TWO positions per CTA,
// 18-chunk double-buffered pipeline, fp16 mma m16n8k16 + ldmatrix.
//   Launched with programmatic stream serialization: starts under xcvt,
//   issues its W prologue LDGs, then griddepcontrol.wait before touching g_xh.

#define PDIM  900
#define KDIM  576
#define ODIM  64
#define OB    (PDIM * ODIM)
#define NCH2  18                    // 2 positions x 9 taps
#define AROWH 72                    // halves per row (64 data + 8 pad)
#define STG_H  (64 * AROWH * 2)     // halves per stage (A + W) = 9216
#define WOFF_H (64 * AROWH)         // 4608
#define STG_B  (STG_H * 2)          // 18432 bytes
#define SMEM_BYTES (2 * STG_B)      // 36864 -> 4 CTAs/SM, L1 keeps ~81KB

#define XN (64 * 32 * 32 * 64)      // 4194304 elements
__device__ __half g_xh[XN];         // 8MB fp16 copy of x

__device__ __forceinline__ uint32_t s2u(const void* p) {
    uint32_t a;
    asm("{.reg .u64 t; cvta.to.shared.u64 t, %1; cvt.u32.u64 %0, t;}"
        : "=r"(a) : "l"(p));
    return a;
}
__device__ __forceinline__ uint32_t packh2(float a, float b) {
    __half2 h = __floats2half2_rn(a, b);
    return *(uint32_t*)&h;
}
__device__ __forceinline__ void cp16(uint32_t dst, const void* src) {
    asm volatile("cp.async.cg.shared.global [%0], [%1], 16;\n"
                 :: "r"(dst), "l"(src));
}

// ------------- kernel 1: x fp32 -> fp16, coalesced, MLP=8, PDL trigger ------
__global__ void __launch_bounds__(256)
xcvt(const float* __restrict__ x)
{
    const int base = blockIdx.x * 8192;          // floats per block
    const int tid  = threadIdx.x;
    float4 v[8];
    #pragma unroll
    for (int k = 0; k < 8; k++)
        asm volatile("ld.global.nc.v4.f32 {%0,%1,%2,%3}, [%4];"
                     : "=f"(v[k].x), "=f"(v[k].y), "=f"(v[k].z), "=f"(v[k].w)
                     : "l"(x + base + k * 1024 + tid * 4));
    #pragma unroll
    for (int k = 0; k < 8; k++) {
        uint2 o;
        o.x = packh2(v[k].x, v[k].y);
        o.y = packh2(v[k].z, v[k].w);
        *(uint2*)(&g_xh[base + k * 1024 + tid * 4]) = o;
    }
    // PDL: this CTA's writes are done -> allow dependent kernel to proceed
    asm volatile("griddepcontrol.launch_dependents;" ::: "memory");
}

// ------------- kernel 2: main GEMM, 2 positions per CTA (R13 config) --------
__global__ void __launch_bounds__(256, 4)
lc2d_f16(const float* __restrict__ kern,
         const float* __restrict__ bias,
         float* __restrict__ out)
{
    const int p0  = blockIdx.x * 2;
    const int p1  = p0 + 1;
    const int rr0 = p0 / 30, cc0 = p0 - rr0 * 30;
    const int rr1 = p1 / 30, cc1 = p1 - rr1 * 30;

    extern __shared__ __half smem[];
    const uint32_t sbase = s2u(smem);
    const int tid = threadIdx.x;

    // ---- producer coords ----
    const int ab  = tid >> 2;     // A row (batch) 0..63
    const int seg = tid & 3;      // 16-half segment 0..3
    const int wo  = tid & 63;     // W output column 0..63
    const int wkg = tid >> 6;     // W k-group 0..3 (16 k each)

    float wr[16];                 // staged W strip (one column, 16 k)

    // A: cp.async fp16 from scratch (chunk c: pos = c<9?p0:p1, tap = c%9)
    auto cpa_chunk = [&](int c, int st) {
        const int tap = (c < 9) ? c : c - 9;
        const int rr  = (c < 9) ? rr0 : rr1;
        const int cc  = (c < 9) ? cc0 : cc1;
        const int di = tap / 3, dj = tap - di * 3;
        const __half* as = g_xh + (((ab * 32) + rr + di) * 32 + (cc + dj)) * 64
                                + seg * 16;
        const uint32_t ad = sbase + (uint32_t)(st * STG_H + ab * AROWH
                                               + seg * 16) * 2u;
        cp16(ad,       as);
        cp16(ad + 16u, as + 8);
    };

    // W: pinned prefetch LDG (asm volatile so ptxas cannot sink)
    auto ldgw_chunk = [&](int c) {
        const int tap = (c < 9) ? c : c - 9;
        const int pp  = (c < 9) ? p0 : p1;
        const float* ws = kern + (size_t)pp * (KDIM * ODIM) + tap * 4096
                               + wkg * 16 * 64 + wo;
        #pragma unroll
        for (int k = 0; k < 16; k++)
            asm volatile("ld.global.nc.f32 %0, [%1];"
                         : "=f"(wr[k]) : "l"(ws + k * 64));
    };

    auto stsw_chunk = [&](int st) {
        uint32_t g[8];
        #pragma unroll
        for (int i = 0; i < 8; i++) g[i] = packh2(wr[2 * i], wr[2 * i + 1]);
        __half* wd = smem + st * STG_H + WOFF_H + wo * AROWH + wkg * 16;
        ((uint4*)wd)[0] = make_uint4(g[0], g[1], g[2], g[3]);
        ((uint4*)wd)[1] = make_uint4(g[4], g[5], g[6], g[7]);
    };

    // ---- consumer coords (identical to validated R6-R13) ----
    const int w    = tid >> 5;
    const int l    = tid & 31;
    const int g_   = l >> 2;
    const int t    = l & 3;
    const int row0 = (w >> 1) * 16;   // 0,16,32,48
    const int col0 = (w & 1) * 32;    // 0,32

    const uint32_t aoff = (uint32_t)(((row0 + (l & 15)) * AROWH
                                      + ((l >> 4) << 3)) * 2);
    const uint32_t boff = (uint32_t)((WOFF_H
                                      + (col0 + ((l >> 4) << 3) + (l & 7)) * AROWH
                                      + (l & 8)) * 2);
    const uint32_t aaddr0 = sbase + aoff;
    const uint32_t baddr0 = sbase + boff;

    float acc[4][4];
    #pragma unroll
    for (int nt = 0; nt < 4; nt++)
        #pragma unroll
        for (int i = 0; i < 4; i++) acc[nt][i] = 0.f;

    auto epilogue = [&](int pp) {
        const float* bp = bias + pp * ODIM;
        float* op = out + pp * ODIM;
        const int r0i = row0 + g_;
        const int r1i = row0 + g_ + 8;
        #pragma unroll
        for (int nt = 0; nt < 4; nt++) {
            const int o = col0 + nt * 8 + 2 * t;
            const float bv0 = bp[o];
            const float bv1 = bp[o + 1];
            float2 v0 = make_float2(fmaxf(acc[nt][0] + bv0, 0.f),
                                    fmaxf(acc[nt][1] + bv1, 0.f));
            float2 v1 = make_float2(fmaxf(acc[nt][2] + bv0, 0.f),
                                    fmaxf(acc[nt][3] + bv1, 0.f));
            *(float2*)(op + (size_t)r0i * OB + o) = v0;
            *(float2*)(op + (size_t)r1i * OB + o) = v1;
        }
    };

    // ---- prologue ----
    ldgw_chunk(0);                 // independent of g_xh: overlaps xcvt
    // PDL: wait for xcvt's stores to be visible before reading g_xh
    asm volatile("griddepcontrol.wait;" ::: "memory");
    cpa_chunk(0, 0);
    asm volatile("cp.async.commit_group;\n" ::: "memory");
    stsw_chunk(0);
    ldgw_chunk(1);
    asm volatile("cp.async.wait_group 0;\n" ::: "memory");
    __syncthreads();

    #pragma unroll 1
    for (int j = 0; j < NCH2; j++) {
        const int st = j & 1;
        if (j + 1 < NCH2) {
            cpa_chunk(j + 1, st ^ 1);
            stsw_chunk(st ^ 1);            // regs hold W chunk j+1
        }
        asm volatile("cp.async.commit_group;\n" ::: "memory");
        if (j + 2 < NCH2) ldgw_chunk(j + 2);

        const uint32_t aa = aaddr0 + (uint32_t)(st * STG_B);
        const uint32_t bb = baddr0 + (uint32_t)(st * STG_B);

        #pragma unroll
        for (int ks = 0; ks < 4; ks++) {
            uint32_t a0, a1, a2, a3, b0, b1, b2, b3, c0, c1, c2, c3;
            asm volatile(
                "ldmatrix.sync.aligned.m8n8.x4.shared.b16 {%0,%1,%2,%3}, [%4];"
                : "=r"(a0), "=r"(a1), "=r"(a2), "=r"(a3)
                : "r"(aa + ks * 32));
            asm volatile(
                "ldmatrix.sync.aligned.m8n8.x4.shared.b16 {%0,%1,%2,%3}, [%4];"
                : "=r"(b0), "=r"(b1), "=r"(b2), "=r"(b3)
                : "r"(bb + ks * 32));
            asm volatile(
                "ldmatrix.sync.aligned.m8n8.x4.shared.b16 {%0,%1,%2,%3}, [%4];"
                : "=r"(c0), "=r"(c1), "=r"(c2), "=r"(c3)
                : "r"(bb + ks * 32 + 16 * AROWH * 2));
            asm volatile(
                "mma.sync.aligned.m16n8k16.row.col.f32.f16.f16.f32 "
                "{%0,%1,%2,%3}, {%4,%5,%6,%7}, {%8,%9}, {%0,%1,%2,%3};"
                : "+f"(acc[0][0]), "+f"(acc[0][1]), "+f"(acc[0][2]), "+f"(acc[0][3])
                : "r"(a0), "r"(a1), "r"(a2), "r"(a3), "r"(b0), "r"(b1));
            asm volatile(
                "mma.sync.aligned.m16n8k16.row.col.f32.f16.f16.f32 "
                "{%0,%1,%2,%3}, {%4,%5,%6,%7}, {%8,%9}, {%0,%1,%2,%3};"
                : "+f"(acc[1][0]), "+f"(acc[1][1]), "+f"(acc[1][2]), "+f"(acc[1][3])
                : "r"(a0), "r"(a1), "r"(a2), "r"(a3), "r"(b2), "r"(b3));
            asm volatile(
                "mma.sync.aligned.m16n8k16.row.col.f32.f16.f16.f32 "
                "{%0,%1,%2,%3}, {%4,%5,%6,%7}, {%8,%9}, {%0,%1,%2,%3};"
                : "+f"(acc[2][0]), "+f"(acc[2][1]), "+f"(acc[2][2]), "+f"(acc[2][3])
                : "r"(a0), "r"(a1), "r"(a2), "r"(a3), "r"(c0), "r"(c1));
            asm volatile(
                "mma.sync.aligned.m16n8k16.row.col.f32.f16.f16.f32 "
                "{%0,%1,%2,%3}, {%4,%5,%6,%7}, {%8,%9}, {%0,%1,%2,%3};"
                : "+f"(acc[3][0]), "+f"(acc[3][1]), "+f"(acc[3][2]), "+f"(acc[3][3])
                : "r"(a0), "r"(a1), "r"(a2), "r"(a3), "r"(c2), "r"(c3));
        }

        if (j == 8) {
            epilogue(p0);          // overlaps in-flight prefetches
            #pragma unroll
            for (int nt = 0; nt < 4; nt++)
                #pragma unroll
                for (int i = 0; i < 4; i++) acc[nt][i] = 0.f;
        }

        asm volatile("cp.async.wait_group 0;\n" ::: "memory");
        __syncthreads();
    }

    epilogue(p1);
}

extern "C" void kernel_launch(void* const* d_in, const int* in_sizes, int n_in,
                              void* d_out, int out_size)
{
    const float* x    = (const float*)d_in[0];   // (64,32,32,64)
    const float* kern = (const float*)d_in[1];   // (900,576,64)
    const float* bias = (const float*)d_in[2];   // (30,30,64)
    float* out = (float*)d_out;                  // (64,30,30,64)

    xcvt<<<XN / 8192, 256>>>(x);                 // 512 blocks, coalesced MLP=8

    // PDL launch: main may start before xcvt completes; it gates itself
    // with griddepcontrol.wait before reading g_xh.
    cudaLaunchConfig_t cfg = {};
    cfg.gridDim  = dim3(PDIM / 2, 1, 1);
    cfg.blockDim = dim3(256, 1, 1);
    cfg.dynamicSmemBytes = SMEM_BYTES;
    cfg.stream = 0;
    cudaLaunchAttribute attr[1];
    attr[0].id = cudaLaunchAttributeProgrammaticStreamSerialization;
    attr[0].val.programmaticStreamSerializationAllowed = 1;
    cfg.attrs = attr;
    cfg.numAttrs = 1;
    cudaLaunchKernelEx(&cfg, lc2d_f16, kern, bias, out);
}

// round 16
// speedup vs baseline: 1.1500x; 1.1500x over previous
#include <cuda_runtime.h>
#include <cuda_fp16.h>
#include <cstdint>

// LocallyConnected2D B=64,H=W=32,C=64,3x3,s1 -> P=900, K=576, O=64
// Kernel 1: x fp32->fp16 once into __device__ scratch (coalesced, MLP=8).
// Kernel 2: grid 450, TWO positions per CTA, 18-chunk double-buffered pipeline.
//   WARP-SPECIALIZED: warps 0-3 consume (32x32 tiles, fp16 mma m16n8k16),
//   warps 4-7 produce (A cp.async fp16 from scratch; W pinned LDG->cvt->STS).

#define PDIM  900
#define KDIM  576
#define ODIM  64
#define OB    (PDIM * ODIM)
#define NCH2  18                    // 2 positions x 9 taps
#define AROWH 72                    // halves per row (64 data + 8 pad)
#define STG_H  (64 * AROWH * 2)     // halves per stage (A + W) = 9216
#define WOFF_H (64 * AROWH)         // 4608
#define STG_B  (STG_H * 2)          // 18432 bytes
#define SMEM_BYTES (2 * STG_B)      // 36864 -> 3 CTAs/SM (grid-limited)

#define XN (64 * 32 * 32 * 64)      // 4194304 elements
__device__ __half g_xh[XN];         // 8MB fp16 copy of x

__device__ __forceinline__ uint32_t s2u(const void* p) {
    uint32_t a;
    asm("{.reg .u64 t; cvta.to.shared.u64 t, %1; cvt.u32.u64 %0, t;}"
        : "=r"(a) : "l"(p));
    return a;
}
__device__ __forceinline__ uint32_t packh2(float a, float b) {
    __half2 h = __floats2half2_rn(a, b);
    return *(uint32_t*)&h;
}
__device__ __forceinline__ void cp16(uint32_t dst, const void* src) {
    asm volatile("cp.async.cg.shared.global [%0], [%1], 16;\n"
                 :: "r"(dst), "l"(src));
}

// ------------- kernel 1: x fp32 -> fp16, coalesced, MLP=8 -------------
__global__ void __launch_bounds__(256)
xcvt(const float* __restrict__ x)
{
    const int base = blockIdx.x * 8192;          // floats per block
    const int tid  = threadIdx.x;
    float4 v[8];
    #pragma unroll
    for (int k = 0; k < 8; k++)
        asm volatile("ld.global.nc.v4.f32 {%0,%1,%2,%3}, [%4];"
                     : "=f"(v[k].x), "=f"(v[k].y), "=f"(v[k].z), "=f"(v[k].w)
                     : "l"(x + base + k * 1024 + tid * 4));
    #pragma unroll
    for (int k = 0; k < 8; k++) {
        uint2 o;
        o.x = packh2(v[k].x, v[k].y);
        o.y = packh2(v[k].z, v[k].w);
        *(uint2*)(&g_xh[base + k * 1024 + tid * 4]) = o;
    }
}

// ------------- kernel 2: warp-specialized main GEMM -------------
__global__ void __launch_bounds__(256, 3)
lc2d_f16(const float* __restrict__ kern,
         const float* __restrict__ bias,
         float* __restrict__ out)
{
    const int p0  = blockIdx.x * 2;
    const int p1  = p0 + 1;
    const int rr0 = p0 / 30, cc0 = p0 - rr0 * 30;
    const int rr1 = p1 / 30, cc1 = p1 - rr1 * 30;

    extern __shared__ __half smem[];
    const uint32_t sbase = s2u(smem);
    const int tid = threadIdx.x;

    if (tid >= 128) {
        // ================= PRODUCER WARPS (4) =================
        const int ptid = tid - 128;           // 0..127
        const int ab  = ptid >> 1;            // A row (batch) 0..63
        const int hr  = ptid & 1;             // half-row 0..1 (32 halves each)
        const int wo  = ptid & 63;            // W output column 0..63
        const int kg2 = ptid >> 6;            // W k-group 0..1 (32 k each)

        float wr[32];                         // staged W strip (one col, 32 k)

        auto cpa_chunk = [&](int c, int st) {
            const int tap = (c < 9) ? c : c - 9;
            const int rr  = (c < 9) ? rr0 : rr1;
            const int cc  = (c < 9) ? cc0 : cc1;
            const int di = tap / 3, dj = tap - di * 3;
            const __half* as = g_xh
                + (((ab * 32) + rr + di) * 32 + (cc + dj)) * 64 + hr * 32;
            const uint32_t ad = sbase + (uint32_t)(st * STG_H + ab * AROWH
                                                   + hr * 32) * 2u;
            #pragma unroll
            for (int i = 0; i < 4; i++) cp16(ad + i * 16u, as + i * 8);
        };

        auto ldgw_chunk = [&](int c) {
            const int tap = (c < 9) ? c : c - 9;
            const int pp  = (c < 9) ? p0 : p1;
            const float* ws = kern + (size_t)pp * (KDIM * ODIM) + tap * 4096
                                   + (kg2 * 32) * 64 + wo;
            #pragma unroll
            for (int k = 0; k < 32; k++)
                asm volatile("ld.global.nc.f32 %0, [%1];"
                             : "=f"(wr[k]) : "l"(ws + k * 64));
        };

        auto stsw_chunk = [&](int st) {
            uint32_t g[16];
            #pragma unroll
            for (int i = 0; i < 16; i++)
                g[i] = packh2(wr[2 * i], wr[2 * i + 1]);
            __half* wd = smem + st * STG_H + WOFF_H + wo * AROWH + kg2 * 32;
            #pragma unroll
            for (int i = 0; i < 4; i++)
                ((uint4*)wd)[i] = make_uint4(g[4 * i], g[4 * i + 1],
                                             g[4 * i + 2], g[4 * i + 3]);
        };

        // prologue
        ldgw_chunk(0);
        cpa_chunk(0, 0);
        asm volatile("cp.async.commit_group;\n" ::: "memory");
        stsw_chunk(0);
        ldgw_chunk(1);
        asm volatile("cp.async.wait_group 0;\n" ::: "memory");
        __syncthreads();

        #pragma unroll 1
        for (int j = 0; j < NCH2; j++) {
            const int st = j & 1;
            if (j + 1 < NCH2) {
                cpa_chunk(j + 1, st ^ 1);
                stsw_chunk(st ^ 1);           // regs hold W chunk j+1
            }
            asm volatile("cp.async.commit_group;\n" ::: "memory");
            if (j + 2 < NCH2) ldgw_chunk(j + 2);
            asm volatile("cp.async.wait_group 0;\n" ::: "memory");
            __syncthreads();
        }
    } else {
        // ================= CONSUMER WARPS (4), 32x32 tiles =================
        const int w    = tid >> 5;            // 0..3
        const int l    = tid & 31;
        const int g_   = l >> 2;
        const int t    = l & 3;
        const int row0 = (w >> 1) * 32;       // 0,32
        const int col0 = (w & 1) * 32;        // 0,32

        const uint32_t aoff = (uint32_t)(((row0 + (l & 15)) * AROWH
                                          + ((l >> 4) << 3)) * 2);
        const uint32_t boff = (uint32_t)((WOFF_H
                                          + (col0 + ((l >> 4) << 3) + (l & 7)) * AROWH
                                          + (l & 8)) * 2);
        const uint32_t aaddr0 = sbase + aoff;
        const uint32_t baddr0 = sbase + boff;
        const uint32_t ROW16 = 16 * AROWH * 2;   // +16 rows/cols in bytes

        float acc[2][4][4];
        #pragma unroll
        for (int rt = 0; rt < 2; rt++)
            #pragma unroll
            for (int nt = 0; nt < 4; nt++)
                #pragma unroll
                for (int i = 0; i < 4; i++) acc[rt][nt][i] = 0.f;

        auto epilogue = [&](int pp) {
            const float* bp = bias + pp * ODIM;
            float* op = out + pp * ODIM;
            #pragma unroll
            for (int rt = 0; rt < 2; rt++) {
                const int r0i = row0 + rt * 16 + g_;
                const int r1i = r0i + 8;
                #pragma unroll
                for (int nt = 0; nt < 4; nt++) {
                    const int o = col0 + nt * 8 + 2 * t;
                    const float bv0 = bp[o];
                    const float bv1 = bp[o + 1];
                    float2 v0 = make_float2(fmaxf(acc[rt][nt][0] + bv0, 0.f),
                                            fmaxf(acc[rt][nt][1] + bv1, 0.f));
                    float2 v1 = make_float2(fmaxf(acc[rt][nt][2] + bv0, 0.f),
                                            fmaxf(acc[rt][nt][3] + bv1, 0.f));
                    *(float2*)(op + (size_t)r0i * OB + o) = v0;
                    *(float2*)(op + (size_t)r1i * OB + o) = v1;
                }
            }
        };

        __syncthreads();   // matches producer prologue barrier

        #pragma unroll 1
        for (int j = 0; j < NCH2; j++) {
            const int st = j & 1;
            const uint32_t aa = aaddr0 + (uint32_t)(st * STG_B);
            const uint32_t bb = baddr0 + (uint32_t)(st * STG_B);

            #pragma unroll
            for (int ks = 0; ks < 4; ks++) {
                uint32_t a0[4], a1[4], b0[4], b1[4];
                asm volatile(
                    "ldmatrix.sync.aligned.m8n8.x4.shared.b16 {%0,%1,%2,%3}, [%4];"
                    : "=r"(a0[0]), "=r"(a0[1]), "=r"(a0[2]), "=r"(a0[3])
                    : "r"(aa + ks * 32));
                asm volatile(
                    "ldmatrix.sync.aligned.m8n8.x4.shared.b16 {%0,%1,%2,%3}, [%4];"
                    : "=r"(a1[0]), "=r"(a1[1]), "=r"(a1[2]), "=r"(a1[3])
                    : "r"(aa + ks * 32 + ROW16));
                asm volatile(
                    "ldmatrix.sync.aligned.m8n8.x4.shared.b16 {%0,%1,%2,%3}, [%4];"
                    : "=r"(b0[0]), "=r"(b0[1]), "=r"(b0[2]), "=r"(b0[3])
                    : "r"(bb + ks * 32));
                asm volatile(
                    "ldmatrix.sync.aligned.m8n8.x4.shared.b16 {%0,%1,%2,%3}, [%4];"
                    : "=r"(b1[0]), "=r"(b1[1]), "=r"(b1[2]), "=r"(b1[3])
                    : "r"(bb + ks * 32 + ROW16));

                #pragma unroll
                for (int rt = 0; rt < 2; rt++) {
                    const uint32_t* A = rt ? a1 : a0;
                    asm volatile(
                        "mma.sync.aligned.m16n8k16.row.col.f32.f16.f16.f32 "
                        "{%0,%1,%2,%3}, {%4,%5,%6,%7}, {%8,%9}, {%0,%1,%2,%3};"
                        : "+f"(acc[rt][0][0]), "+f"(acc[rt][0][1]),
                          "+f"(acc[rt][0][2]), "+f"(acc[rt][0][3])
                        : "r"(A[0]), "r"(A[1]), "r"(A[2]), "r"(A[3]),
                          "r"(b0[0]), "r"(b0[1]));
                    asm volatile(
                        "mma.sync.aligned.m16n8k16.row.col.f32.f16.f16.f32 "
                        "{%0,%1,%2,%3}, {%4,%5,%6,%7}, {%8,%9}, {%0,%1,%2,%3};"
                        : "+f"(acc[rt][1][0]), "+f"(acc[rt][1][1]),
                          "+f"(acc[rt][1][2]), "+f"(acc[rt][1][3])
                        : "r"(A[0]), "r"(A[1]), "r"(A[2]), "r"(A[3]),
                          "r"(b0[2]), "r"(b0[3]));
                    asm volatile(
                        "mma.sync.aligned.m16n8k16.row.col.f32.f16.f16.f32 "
                        "{%0,%1,%2,%3}, {%4,%5,%6,%7}, {%8,%9}, {%0,%1,%2,%3};"
                        : "+f"(acc[rt][2][0]), "+f"(acc[rt][2][1]),
                          "+f"(acc[rt][2][2]), "+f"(acc[rt][2][3])
                        : "r"(A[0]), "r"(A[1]), "r"(A[2]), "r"(A[3]),
                          "r"(b1[0]), "r"(b1[1]));
                    asm volatile(
                        "mma.sync.aligned.m16n8k16.row.col.f32.f16.f16.f32 "
                        "{%0,%1,%2,%3}, {%4,%5,%6,%7}, {%8,%9}, {%0,%1,%2,%3};"
                        : "+f"(acc[rt][3][0]), "+f"(acc[rt][3][1]),
                          "+f"(acc[rt][3][2]), "+f"(acc[rt][3][3])
                        : "r"(A[0]), "r"(A[1]), "r"(A[2]), "r"(A[3]),
                          "r"(b1[2]), "r"(b1[3]));
                }
            }

            if (j == 8) {
                epilogue(p0);
                #pragma unroll
                for (int rt = 0; rt < 2; rt++)
                    #pragma unroll
                    for (int nt = 0; nt < 4; nt++)
                        #pragma unroll
                        for (int i = 0; i < 4; i++) acc[rt][nt][i] = 0.f;
            }
            __syncthreads();
        }

        epilogue(p1);
    }
}

extern "C" void kernel_launch(void* const* d_in, const int* in_sizes, int n_in,
                              void* d_out, int out_size)
{
    const float* x    = (const float*)d_in[0];   // (64,32,32,64)
    const float* kern = (const float*)d_in[1];   // (900,576,64)
    const float* bias = (const float*)d_in[2];   // (30,30,64)
    float* out = (float*)d_out;                  // (64,30,30,64)

    xcvt<<<XN / 8192, 256>>>(x);                 // 512 blocks, coalesced MLP=8
    lc2d_f16<<<PDIM / 2, 256, SMEM_BYTES>>>(kern, bias, out);
}

// round 17
// speedup vs baseline: 1.1992x; 1.0427x over previous
#include <cuda_runtime.h>
#include <cuda_fp16.h>
#include <cstdint>

// LocallyConnected2D B=64,H=W=32,C=64,3x3,s1 -> P=900, K=576, O=64
// Kernel 1: x fp32->fp16 once into __device__ scratch (coalesced, MLP=8).
// Kernel 2 (= R13 config + relaxed reg bound + unroll-2): grid 450, TWO
// positions per CTA, 18-chunk double-buffered pipeline, fp16 mma m16n8k16.
//   A: cp.async fp16 from scratch (2-stage, wait_group 0).
//   W: pinned LDG->cvt->STS register-staged (the DRAM stream), 2-chunk lookahead.

#define PDIM  900
#define KDIM  576
#define ODIM  64
#define OB    (PDIM * ODIM)
#define NCH2  18                    // 2 positions x 9 taps
#define AROWH 72                    // halves per row (64 data + 8 pad)
#define STG_H  (64 * AROWH * 2)     // halves per stage (A + W) = 9216
#define WOFF_H (64 * AROWH)         // 4608
#define STG_B  (STG_H * 2)          // 18432 bytes
#define SMEM_BYTES (2 * STG_B)      // 36864 -> 3.04 CTAs/SM (grid-limited)

#define XN (64 * 32 * 32 * 64)      // 4194304 elements
__device__ __half g_xh[XN];         // 8MB fp16 copy of x

__device__ __forceinline__ uint32_t s2u(const void* p) {
    uint32_t a;
    asm("{.reg .u64 t; cvta.to.shared.u64 t, %1; cvt.u32.u64 %0, t;}"
        : "=r"(a) : "l"(p));
    return a;
}
__device__ __forceinline__ uint32_t packh2(float a, float b) {
    __half2 h = __floats2half2_rn(a, b);
    return *(uint32_t*)&h;
}
__device__ __forceinline__ void cp16(uint32_t dst, const void* src) {
    asm volatile("cp.async.cg.shared.global [%0], [%1], 16;\n"
                 :: "r"(dst), "l"(src));
}

// ------------- kernel 1: x fp32 -> fp16, coalesced, MLP=8 -------------
__global__ void __launch_bounds__(256)
xcvt(const float* __restrict__ x)
{
    const int base = blockIdx.x * 8192;          // floats per block
    const int tid  = threadIdx.x;
    float4 v[8];
    #pragma unroll
    for (int k = 0; k < 8; k++)
        asm volatile("ld.global.nc.v4.f32 {%0,%1,%2,%3}, [%4];"
                     : "=f"(v[k].x), "=f"(v[k].y), "=f"(v[k].z), "=f"(v[k].w)
                     : "l"(x + base + k * 1024 + tid * 4));
    #pragma unroll
    for (int k = 0; k < 8; k++) {
        uint2 o;
        o.x = packh2(v[k].x, v[k].y);
        o.y = packh2(v[k].z, v[k].w);
        *(uint2*)(&g_xh[base + k * 1024 + tid * 4]) = o;
    }
}

// ------------- kernel 2: main GEMM, 2 positions per CTA -------------
__global__ void __launch_bounds__(256, 3)
lc2d_f16(const float* __restrict__ kern,
         const float* __restrict__ bias,
         float* __restrict__ out)
{
    const int p0  = blockIdx.x * 2;
    const int p1  = p0 + 1;
    const int rr0 = p0 / 30, cc0 = p0 - rr0 * 30;
    const int rr1 = p1 / 30, cc1 = p1 - rr1 * 30;

    extern __shared__ __half smem[];
    const uint32_t sbase = s2u(smem);
    const int tid = threadIdx.x;

    // ---- producer coords ----
    const int ab  = tid >> 2;     // A row (batch) 0..63
    const int seg = tid & 3;      // 16-half segment 0..3
    const int wo  = tid & 63;     // W output column 0..63
    const int wkg = tid >> 6;     // W k-group 0..3 (16 k each)

    float wr[16];                 // staged W strip (one column, 16 k)

    // A: cp.async fp16 from scratch (chunk c: pos = c<9?p0:p1, tap = c%9)
    auto cpa_chunk = [&](int c, int st) {
        const int tap = (c < 9) ? c : c - 9;
        const int rr  = (c < 9) ? rr0 : rr1;
        const int cc  = (c < 9) ? cc0 : cc1;
        const int di = tap / 3, dj = tap - di * 3;
        const __half* as = g_xh + (((ab * 32) + rr + di) * 32 + (cc + dj)) * 64
                                + seg * 16;
        const uint32_t ad = sbase + (uint32_t)(st * STG_H + ab * AROWH
                                               + seg * 16) * 2u;
        cp16(ad,       as);
        cp16(ad + 16u, as + 8);
    };

    // W: pinned prefetch LDG (asm volatile so ptxas cannot sink)
    auto ldgw_chunk = [&](int c) {
        const int tap = (c < 9) ? c : c - 9;
        const int pp  = (c < 9) ? p0 : p1;
        const float* ws = kern + (size_t)pp * (KDIM * ODIM) + tap * 4096
                               + wkg * 16 * 64 + wo;
        #pragma unroll
        for (int k = 0; k < 16; k++)
            asm volatile("ld.global.nc.f32 %0, [%1];"
                         : "=f"(wr[k]) : "l"(ws + k * 64));
    };

    auto stsw_chunk = [&](int st) {
        uint32_t g[8];
        #pragma unroll
        for (int i = 0; i < 8; i++) g[i] = packh2(wr[2 * i], wr[2 * i + 1]);
        __half* wd = smem + st * STG_H + WOFF_H + wo * AROWH + wkg * 16;
        ((uint4*)wd)[0] = make_uint4(g[0], g[1], g[2], g[3]);
        ((uint4*)wd)[1] = make_uint4(g[4], g[5], g[6], g[7]);
    };

    // ---- consumer coords (identical to validated R6-R13) ----
    const int w    = tid >> 5;
    const int l    = tid & 31;
    const int g_   = l >> 2;
    const int t    = l & 3;
    const int row0 = (w >> 1) * 16;   // 0,16,32,48
    const int col0 = (w & 1) * 32;    // 0,32

    const uint32_t aoff = (uint32_t)(((row0 + (l & 15)) * AROWH
                                      + ((l >> 4) << 3)) * 2);
    const uint32_t boff = (uint32_t)((WOFF_H
                                      + (col0 + ((l >> 4) << 3) + (l & 7)) * AROWH
                                      + (l & 8)) * 2);
    const uint32_t aaddr0 = sbase + aoff;
    const uint32_t baddr0 = sbase + boff;

    float acc[4][4];
    #pragma unroll
    for (int nt = 0; nt < 4; nt++)
        #pragma unroll
        for (int i = 0; i < 4; i++) acc[nt][i] = 0.f;

    auto epilogue = [&](int pp) {
        const float* bp = bias + pp * ODIM;
        float* op = out + pp * ODIM;
        const int r0i = row0 + g_;
        const int r1i = row0 + g_ + 8;
        #pragma unroll
        for (int nt = 0; nt < 4; nt++) {
            const int o = col0 + nt * 8 + 2 * t;
            const float bv0 = bp[o];
            const float bv1 = bp[o + 1];
            float2 v0 = make_float2(fmaxf(acc[nt][0] + bv0, 0.f),
                                    fmaxf(acc[nt][1] + bv1, 0.f));
            float2 v1 = make_float2(fmaxf(acc[nt][2] + bv0, 0.f),
                                    fmaxf(acc[nt][3] + bv1, 0.f));
            *(float2*)(op + (size_t)r0i * OB + o) = v0;
            *(float2*)(op + (size_t)r1i * OB + o) = v1;
        }
    };

    // ---- prologue ----
    ldgw_chunk(0);
    cpa_chunk(0, 0);
    asm volatile("cp.async.commit_group;\n" ::: "memory");
    stsw_chunk(0);
    ldgw_chunk(1);
    asm volatile("cp.async.wait_group 0;\n" ::: "memory");
    __syncthreads();

    #pragma unroll 2
    for (int j = 0; j < NCH2; j++) {
        const int st = j & 1;
        if (j + 1 < NCH2) {
            cpa_chunk(j + 1, st ^ 1);
            stsw_chunk(st ^ 1);            // regs hold W chunk j+1
        }
        asm volatile("cp.async.commit_group;\n" ::: "memory");
        if (j + 2 < NCH2) ldgw_chunk(j + 2);

        const uint32_t aa = aaddr0 + (uint32_t)(st * STG_B);
        const uint32_t bb = baddr0 + (uint32_t)(st * STG_B);

        #pragma unroll
        for (int ks = 0; ks < 4; ks++) {
            uint32_t a0, a1, a2, a3, b0, b1, b2, b3, c0, c1, c2, c3;
            asm volatile(
                "ldmatrix.sync.aligned.m8n8.x4.shared.b16 {%0,%1,%2,%3}, [%4];"
                : "=r"(a0), "=r"(a1), "=r"(a2), "=r"(a3)
                : "r"(aa + ks * 32));
            asm volatile(
                "ldmatrix.sync.aligned.m8n8.x4.shared.b16 {%0,%1,%2,%3}, [%4];"
                : "=r"(b0), "=r"(b1), "=r"(b2), "=r"(b3)
                : "r"(bb + ks * 32));
            asm volatile(
                "ldmatrix.sync.aligned.m8n8.x4.shared.b16 {%0,%1,%2,%3}, [%4];"
                : "=r"(c0), "=r"(c1), "=r"(c2), "=r"(c3)
                : "r"(bb + ks * 32 + 16 * AROWH * 2));
            asm volatile(
                "mma.sync.aligned.m16n8k16.row.col.f32.f16.f16.f32 "
                "{%0,%1,%2,%3}, {%4,%5,%6,%7}, {%8,%9}, {%0,%1,%2,%3};"
                : "+f"(acc[0][0]), "+f"(acc[0][1]), "+f"(acc[0][2]), "+f"(acc[0][3])
                : "r"(a0), "r"(a1), "r"(a2), "r"(a3), "r"(b0), "r"(b1));
            asm volatile(
                "mma.sync.aligned.m16n8k16.row.col.f32.f16.f16.f32 "
                "{%0,%1,%2,%3}, {%4,%5,%6,%7}, {%8,%9}, {%0,%1,%2,%3};"
                : "+f"(acc[1][0]), "+f"(acc[1][1]), "+f"(acc[1][2]), "+f"(acc[1][3])
                : "r"(a0), "r"(a1), "r"(a2), "r"(a3), "r"(b2), "r"(b3));
            asm volatile(
                "mma.sync.aligned.m16n8k16.row.col.f32.f16.f16.f32 "
                "{%0,%1,%2,%3}, {%4,%5,%6,%7}, {%8,%9}, {%0,%1,%2,%3};"
                : "+f"(acc[2][0]), "+f"(acc[2][1]), "+f"(acc[2][2]), "+f"(acc[2][3])
                : "r"(a0), "r"(a1), "r"(a2), "r"(a3), "r"(c0), "r"(c1));
            asm volatile(
                "mma.sync.aligned.m16n8k16.row.col.f32.f16.f16.f32 "
                "{%0,%1,%2,%3}, {%4,%5,%6,%7}, {%8,%9}, {%0,%1,%2,%3};"
                : "+f"(acc[3][0]), "+f"(acc[3][1]), "+f"(acc[3][2]), "+f"(acc[3][3])
                : "r"(a0), "r"(a1), "r"(a2), "r"(a3), "r"(c2), "r"(c3));
        }

        if (j == 8) {
            epilogue(p0);          // overlaps in-flight prefetches
            #pragma unroll
            for (int nt = 0; nt < 4; nt++)
                #pragma unroll
                for (int i = 0; i < 4; i++) acc[nt][i] = 0.f;
        }

        asm volatile("cp.async.wait_group 0;\n" ::: "memory");
        __syncthreads();
    }

    epilogue(p1);
}

extern "C" void kernel_launch(void* const* d_in, const int* in_sizes, int n_in,
                              void* d_out, int out_size)
{
    const float* x    = (const float*)d_in[0];   // (64,32,32,64)
    const float* kern = (const float*)d_in[1];   // (900,576,64)
    const float* bias = (const float*)d_in[2];   // (30,30,64)
    float* out = (float*)d_out;                  // (64,30,30,64)

    xcvt<<<XN / 8192, 256>>>(x);                 // 512 blocks, coalesced MLP=8
    lc2d_f16<<<PDIM / 2, 256, SMEM_BYTES>>>(kern, bias, out);
}